// round 7
// baseline (speedup 1.0000x reference)
#include <cuda_runtime.h>
#include <cuda_fp16.h>
#include <math.h>

#define B_ 256
#define T_ 512
#define N_ 512
#define H_ 256
#define CHUNK 64

typedef unsigned long long u64;
typedef unsigned u32;

// ---------------- scratch (device globals; allocation-free) ----------------
__device__ u32   g_Eh[(size_t)B_ * N_ * (H_ / 2)];   // enc_proj half2 [b][n][h2]
__device__ u32   g_Qh[(size_t)T_ * B_ * (H_ / 2)];   // q       half2 [t][b][h2]
__device__ float g_Hall[(size_t)T_ * B_ * H_];       // hiddens f32   [t][b][h]
__device__ float g_hid0[B_ * H_];                    // hid at chunk boundary
__device__ float g_cell[B_ * H_];                    // cell at chunk boundary

// ---------------- fast-math helpers ----------------
__device__ __forceinline__ float tanha(float x) {
    float y; asm("tanh.approx.f32 %0, %1;" : "=f"(y) : "f"(x)); return y;
}
__device__ __forceinline__ float sigma_(float x) {
    return fmaf(0.5f, tanha(0.5f * x), 0.5f);
}
__device__ __forceinline__ u64 ffma2(u64 a, u64 b, u64 c) {
    u64 r; asm("fma.rn.f32x2 %0, %1, %2, %3;" : "=l"(r) : "l"(a), "l"(b), "l"(c));
    return r;
}
__device__ __forceinline__ u64 fdup2(float x) {
    u64 r; asm("mov.b64 %0, {%1, %1};" : "=l"(r) : "f"(x)); return r;
}
__device__ __forceinline__ float fsum2(u64 a) {
    float lo, hi; asm("mov.b64 {%0, %1}, %2;" : "=f"(lo), "=f"(hi) : "l"(a));
    return lo + hi;
}
__device__ __forceinline__ float2 funpk(u64 a) {
    float2 f; asm("mov.b64 {%0, %1}, %2;" : "=f"(f.x), "=f"(f.y) : "l"(a));
    return f;
}
__device__ __forceinline__ u32 packh2(float a, float b) {
    __half2 h = __floats2half2_rn(a, b);
    return *reinterpret_cast<u32*>(&h);
}
// half(low 16 bits) -> float, pure ALU (exact for normals)
__device__ __forceinline__ float h2f_fast(u32 hb) {
    u32 r = ((hb & 0x8000u) << 16) + ((hb & 0x7FFFu) << 13) + 0x38000000u;
    return __uint_as_float(r);
}
// XOR block swizzle for gemm W-tile smem
__device__ __forceinline__ int wperm(int k) {
    int b = k >> 3;
    return (((b ^ (b >> 2)) & 15) << 3) | (k & 7);
}
__device__ __forceinline__ u32 smem_u32(const void* p) {
    u32 a;
    asm("{ .reg .u64 t; cvta.to.shared.u64 t, %1; cvt.u32.u64 %0, t; }"
        : "=r"(a) : "l"(p));
    return a;
}
// store float to same smem offset in cluster CTA `rank` (incl. self)
__device__ __forceinline__ void st_cluster_f32(u32 laddr, u32 rank, float v) {
    u32 raddr;
    asm volatile("mapa.shared::cluster.u32 %0, %1, %2;"
                 : "=r"(raddr) : "r"(laddr), "r"(rank));
    asm volatile("st.shared::cluster.f32 [%0], %1;" :: "r"(raddr), "f"(v));
}

// ---------------------------------------------------------------------------
// GEMM: OutH[m][k](half2-packed) = sum_h X[m][h] * W[k][h]
// ---------------------------------------------------------------------------
__global__ __launch_bounds__(256) void gemm_kernel(
    const float* __restrict__ X, const float* __restrict__ W,
    u32* __restrict__ OutH) {
    __shared__ __align__(16) float Xs[16][132];
    __shared__ __align__(16) float Ws[16][132];
    const int tid = threadIdx.x;

    const size_t m0 = (size_t)blockIdx.x * 128;
    const int k0 = blockIdx.y * 128;
    const int f = tid & 3, r = tid >> 2;
    const int tm = tid >> 4, tk = tid & 15;
    const int wko = wperm(tk * 8);

    const float* Xp = X + (m0 + r) * H_ + f * 4;
    const float* Wp = W + (size_t)(k0 + r) * H_ + f * 4;
    const int rp0 = wperm(r), rp1 = wperm(r + 64);

    u64 acc[8][4];
#pragma unroll
    for (int i = 0; i < 8; i++)
#pragma unroll
        for (int j = 0; j < 4; j++) acc[i][j] = 0ULL;

    for (int h0 = 0; h0 < H_; h0 += 16) {
        float4 x0 = *(const float4*)(Xp + h0);
        float4 x1 = *(const float4*)(Xp + h0 + (size_t)64 * H_);
        float4 w0 = *(const float4*)(Wp + h0);
        float4 w1 = *(const float4*)(Wp + h0 + (size_t)64 * H_);
        __syncthreads();
        Xs[f * 4 + 0][r] = x0.x; Xs[f * 4 + 1][r] = x0.y;
        Xs[f * 4 + 2][r] = x0.z; Xs[f * 4 + 3][r] = x0.w;
        Xs[f * 4 + 0][r + 64] = x1.x; Xs[f * 4 + 1][r + 64] = x1.y;
        Xs[f * 4 + 2][r + 64] = x1.z; Xs[f * 4 + 3][r + 64] = x1.w;
        Ws[f * 4 + 0][rp0] = w0.x; Ws[f * 4 + 1][rp0] = w0.y;
        Ws[f * 4 + 2][rp0] = w0.z; Ws[f * 4 + 3][rp0] = w0.w;
        Ws[f * 4 + 0][rp1] = w1.x; Ws[f * 4 + 1][rp1] = w1.y;
        Ws[f * 4 + 2][rp1] = w1.z; Ws[f * 4 + 3][rp1] = w1.w;
        __syncthreads();
#pragma unroll
        for (int hh = 0; hh < 16; hh++) {
            float xr[8];
            *(float4*)&xr[0] = *(const float4*)&Xs[hh][tm * 8];
            *(float4*)&xr[4] = *(const float4*)&Xs[hh][tm * 8 + 4];
            ulonglong2 wa = *(const ulonglong2*)&Ws[hh][wko];
            ulonglong2 wb = *(const ulonglong2*)&Ws[hh][wko + 4];
#pragma unroll
            for (int i = 0; i < 8; i++) {
                u64 xd = fdup2(xr[i]);
                acc[i][0] = ffma2(xd, wa.x, acc[i][0]);
                acc[i][1] = ffma2(xd, wa.y, acc[i][1]);
                acc[i][2] = ffma2(xd, wb.x, acc[i][2]);
                acc[i][3] = ffma2(xd, wb.y, acc[i][3]);
            }
        }
    }
#pragma unroll
    for (int i = 0; i < 8; i++) {
        float2 p0 = funpk(acc[i][0]), p1 = funpk(acc[i][1]);
        float2 p2 = funpk(acc[i][2]), p3 = funpk(acc[i][3]);
        uint4 o;
        o.x = packh2(p0.x, p0.y); o.y = packh2(p1.x, p1.y);
        o.z = packh2(p2.x, p2.y); o.w = packh2(p3.x, p3.y);
        u32* op = OutH + (m0 + tm * 8 + i) * (H_ / 2) + (k0 >> 1) + tk * 4;
        *(uint4*)op = o;
    }
}

// ---------------------------------------------------------------------------
// LSTM scan chunk: 16 clusters x 8 CTAs, 512 threads/CTA.
// Compute: warp w -> rh=w&1 (8 batch rows), hq=w>>1 (32-h chunk); partials to
// P[hq][bat][128]. Reduce: warp=batch row, lane=h-col, cell in register.
// hid exchange: DSMEM push (st.shared::cluster to all 8 CTAs) + cluster barrier.
// No L2 barrier, no g_hid round-trip inside the chunk.
// ---------------------------------------------------------------------------
#define WSS 260
#define SCAN_SMEM ((128 * WSS + 16 * 256 + 8 * 16 * 128 + 128) * 4)

#define PDOT4(A, wv, hv)                 \
    A = ffma2((wv).x, (hv).x, A);        \
    A = ffma2((wv).y, (hv).y, A)

__global__ __launch_bounds__(512) __cluster_dims__(8, 1, 1)
void scan_kernel(
    const float* __restrict__ W_ih, const float* __restrict__ W_hh,
    const float* __restrict__ b_ih, const float* __restrict__ b_hh,
    int t0) {
    extern __shared__ float sm[];
    float* Ws = sm;                       // [128][WSS] gate-rows x h
    float* hid_s = Ws + 128 * WSS;        // [16][256]
    float* P = hid_s + 16 * 256;          // [8 hq][16 bat][128 gr]
    float* bcs = P + 8 * 16 * 128;        // [128]

    const int tid = threadIdx.x;
    const int grp = blockIdx.x >> 3, j = blockIdx.x & 7;   // j == cluster rank
    const int r0 = grp * 16, hbase = j * 32;
    const int w = tid >> 5, lane = tid & 31;

    for (int idx = tid; idx < 128 * 256; idx += 512) {
        int q = idx >> 8, h = idx & 255;
        int row = (q >> 5) * 256 + hbase + (q & 31);   // gate-type*256 + hcol
        size_t ww = (size_t)row * H_ + h;
        Ws[q * WSS + h] = W_ih[ww] + W_hh[ww];
    }
    if (tid < 128) {
        int row = (tid >> 5) * 256 + hbase + (tid & 31);
        bcs[tid] = b_ih[row] + b_hh[row];
    }
    float cell;
    if (t0 == 0) {
        for (int idx = tid; idx < 16 * 256; idx += 512) hid_s[idx] = 0.f;
        cell = 0.f;
    } else {
        const float4* src = (const float4*)&g_hid0[r0 * H_];
        for (int i2 = tid; i2 < 1024; i2 += 512)
            *(float4*)&hid_s[i2 * 4] = __ldcg(src + i2);
        cell = __ldcg(&g_cell[(r0 + w) * H_ + hbase + lane]);
    }
    __syncthreads();
    // cluster-wide: everyone's hid_s/weights ready before peers may push
    asm volatile("barrier.cluster.arrive.aligned;" ::: "memory");
    asm volatile("barrier.cluster.wait.aligned;" ::: "memory");

    const int rh = w & 1, hq = w >> 1, hb = hq * 32;
    const float* wp0 = &Ws[(0 * 32 + lane) * WSS + hb];
    const float* wp1 = &Ws[(1 * 32 + lane) * WSS + hb];
    const float* wp2 = &Ws[(2 * 32 + lane) * WSS + hb];
    const float* wp3 = &Ws[(3 * 32 + lane) * WSS + hb];
    const float* hp = &hid_s[(rh * 8) * 256 + hb];
    float* pw = &P[hq * 2048 + (rh * 8) * 128 + lane];
    const float* pr = &P[w * 128 + lane];
    const u32 hid_addr = smem_u32(&hid_s[w * 256 + hbase + lane]);

    for (int tt = 0; tt < CHUNK; tt++) {
        const int t = t0 + tt;
        u64 acc[4][8];
#pragma unroll
        for (int g = 0; g < 4; g++)
#pragma unroll
            for (int r = 0; r < 8; r++) acc[g][r] = 0ULL;

#pragma unroll 2
        for (int c = 0; c < 32; c += 4) {
            ulonglong2 w0 = *(const ulonglong2*)(wp0 + c);
            ulonglong2 w1 = *(const ulonglong2*)(wp1 + c);
            ulonglong2 w2 = *(const ulonglong2*)(wp2 + c);
            ulonglong2 w3 = *(const ulonglong2*)(wp3 + c);
#pragma unroll
            for (int r = 0; r < 8; r++) {
                ulonglong2 hv = *(const ulonglong2*)(hp + r * 256 + c);
                PDOT4(acc[0][r], w0, hv);
                PDOT4(acc[1][r], w1, hv);
                PDOT4(acc[2][r], w2, hv);
                PDOT4(acc[3][r], w3, hv);
            }
        }
        // write partials (stride-1: 1 wavefront per STS)
#pragma unroll
        for (int g = 0; g < 4; g++)
#pragma unroll
            for (int r = 0; r < 8; r++)
                pw[r * 128 + g * 32] = fsum2(acc[g][r]);
        __syncthreads();

        // reduce + gate math: warp w = batch row, lane = h-col
        float gate[4];
#pragma unroll
        for (int ty = 0; ty < 4; ty++) {
            float s = bcs[ty * 32 + lane];
#pragma unroll
            for (int k = 0; k < 8; k++) s += pr[k * 2048 + ty * 32];
            gate[ty] = s;
        }
        cell = sigma_(gate[1]) * cell + sigma_(gate[0]) * tanha(gate[2]);
        float hd = sigma_(gate[3]) * tanha(cell);
        g_Hall[((size_t)t * B_ + r0 + w) * H_ + hbase + lane] = hd;
        // push hid to all 8 CTAs' hid_s (incl. self) via DSMEM
#pragma unroll
        for (u32 c = 0; c < 8; c++) st_cluster_f32(hid_addr, c, hd);

        // cluster barrier: orders all pushes before next step's reads
        asm volatile("barrier.cluster.arrive.aligned;" ::: "memory");
        asm volatile("barrier.cluster.wait.aligned;" ::: "memory");
    }

    g_hid0[(r0 + w) * H_ + hbase + lane] = hid_s[w * 256 + hbase + lane];
    g_cell[(r0 + w) * H_ + hbase + lane] = cell;
}

// ---------------------------------------------------------------------------
// Attention: out[b][t][n] = sum_h v[h]*tanh(E[b][n][h]+Q[t][b][h])
// All-half pipeline: HADD2 -> tanh.f16x2 -> HFMA2 (chunked) -> ALU widen
// (at the MUFU value-rate floor; frozen)
// ---------------------------------------------------------------------------
#define ASU 132
#define ATTN_SMEM ((2 * 64 * ASU + 128) * 4)

#define HADD2A(r, a, b) asm("add.rn.f16x2 %0, %1, %2;" : "=r"(r) : "r"(a), "r"(b))
#define TANH2A(r, a)    asm("tanh.approx.f16x2 %0, %1;" : "=r"(r) : "r"(a))
#define HFMA2A(d, a, b) asm("fma.rn.f16x2 %0, %1, %2, %3;" : "=r"(d) : "r"(a), "r"(b), "r"(d))

#define ATC(accr, qc, ec, vc)            \
    { u32 s_, t_;                        \
      HADD2A(s_, (qc), (ec));            \
      TANH2A(t_, s_);                    \
      HFMA2A((accr), (vc), t_); }

#define AT4H(accr, q4, e4, v4)           \
    ATC(accr, (q4).x, (e4).x, (v4).x);   \
    ATC(accr, (q4).y, (e4).y, (v4).y);   \
    ATC(accr, (q4).z, (e4).z, (v4).z);   \
    ATC(accr, (q4).w, (e4).w, (v4).w)

__global__ __launch_bounds__(256) void attn_kernel(
    const float* __restrict__ v, float* __restrict__ out) {
    extern __shared__ u32 smu[];
    u32* Qs = smu;               // [64][ASU] half2
    u32* Es = Qs + 64 * ASU;     // [64][ASU] half2
    u32* vs = Es + 64 * ASU;     // [128] half2

    const int tid = threadIdx.x;
    const int b = blockIdx.z, t0 = blockIdx.y << 6, n0 = blockIdx.x << 6;

    if (tid < 128) {
        float2 vv = ((const float2*)v)[tid];
        vs[tid] = packh2(vv.x, vv.y);
    }
    for (int i = tid; i < 2048; i += 256) {
        int row = i >> 5, c4 = i & 31;
        uint4 q = __ldg((const uint4*)(g_Qh + ((size_t)(t0 + row) * B_ + b) * (H_ / 2)) + c4);
        *(uint4*)&Qs[row * ASU + c4 * 4] = q;
        uint4 e = __ldg((const uint4*)(g_Eh + ((size_t)b * N_ + n0 + row) * (H_ / 2)) + c4);
        *(uint4*)&Es[row * ASU + c4 * 4] = e;
    }
    __syncthreads();

    const int tx = tid & 15, ty = tid >> 4;
    float acc[4][4];
#pragma unroll
    for (int i = 0; i < 4; i++)
#pragma unroll
        for (int jj = 0; jj < 4; jj++) acc[i][jj] = 0.f;

    const u32* qp = &Qs[ty * ASU];
    const u32* ep = &Es[tx * ASU];

#pragma unroll 1
    for (int c = 0; c < 16; c++) {
        u32 hacc[4][4];
#pragma unroll
        for (int i = 0; i < 4; i++)
#pragma unroll
            for (int jj = 0; jj < 4; jj++) hacc[i][jj] = 0u;

#pragma unroll
        for (int s = 0; s < 2; s++) {
            const int o = (c * 2 + s) * 4;
            uint4 vv = *(const uint4*)&vs[o];
            uint4 q0 = *(const uint4*)(qp + o);
            uint4 q1 = *(const uint4*)(qp + 16 * ASU + o);
            uint4 q2 = *(const uint4*)(qp + 32 * ASU + o);
            uint4 q3 = *(const uint4*)(qp + 48 * ASU + o);
            uint4 e0 = *(const uint4*)(ep + o);
            uint4 e1 = *(const uint4*)(ep + 16 * ASU + o);
            uint4 e2 = *(const uint4*)(ep + 32 * ASU + o);
            uint4 e3 = *(const uint4*)(ep + 48 * ASU + o);
            AT4H(hacc[0][0], q0, e0, vv); AT4H(hacc[0][1], q0, e1, vv);
            AT4H(hacc[0][2], q0, e2, vv); AT4H(hacc[0][3], q0, e3, vv);
            AT4H(hacc[1][0], q1, e0, vv); AT4H(hacc[1][1], q1, e1, vv);
            AT4H(hacc[1][2], q1, e2, vv); AT4H(hacc[1][3], q1, e3, vv);
            AT4H(hacc[2][0], q2, e0, vv); AT4H(hacc[2][1], q2, e1, vv);
            AT4H(hacc[2][2], q2, e2, vv); AT4H(hacc[2][3], q2, e3, vv);
            AT4H(hacc[3][0], q3, e0, vv); AT4H(hacc[3][1], q3, e1, vv);
            AT4H(hacc[3][2], q3, e2, vv); AT4H(hacc[3][3], q3, e3, vv);
        }
#pragma unroll
        for (int i = 0; i < 4; i++)
#pragma unroll
            for (int jj = 0; jj < 4; jj++) {
                u32 hb = hacc[i][jj];
                acc[i][jj] += h2f_fast(hb) + h2f_fast(hb >> 16);
            }
    }

#pragma unroll
    for (int i = 0; i < 4; i++) {
        float* op = out + ((size_t)b * T_ + t0 + ty + 16 * i) * N_ + n0 + tx;
#pragma unroll
        for (int jj = 0; jj < 4; jj++) op[16 * jj] = acc[i][jj];
    }
}

// ---------------------------------------------------------------------------
extern "C" void kernel_launch(void* const* d_in, const int* in_sizes, int n_in,
                              void* d_out, int out_size) {
    const float* enc   = (const float*)d_in[0];
    const float* W_ih  = (const float*)d_in[1];
    const float* W_hh  = (const float*)d_in[2];
    const float* b_ih  = (const float*)d_in[3];
    const float* b_hh  = (const float*)d_in[4];
    const float* W_ref = (const float*)d_in[5];
    const float* W_q   = (const float*)d_in[6];
    const float* v     = (const float*)d_in[7];
    float* out = (float*)d_out;

    cudaFuncSetAttribute(scan_kernel, cudaFuncAttributeMaxDynamicSharedMemorySize, SCAN_SMEM);
    cudaFuncSetAttribute(attn_kernel, cudaFuncAttributeMaxDynamicSharedMemorySize, ATTN_SMEM);

    void *pEh, *pQh, *pH;
    cudaGetSymbolAddress(&pEh, g_Eh);
    cudaGetSymbolAddress(&pQh, g_Qh);
    cudaGetSymbolAddress(&pH, g_Hall);

    gemm_kernel<<<dim3(1024, 2), 256>>>(enc, W_ref, (u32*)pEh);
    for (int t0 = 0; t0 < T_; t0 += CHUNK)
        scan_kernel<<<128, 512, SCAN_SMEM>>>(W_ih, W_hh, b_ih, b_hh, t0);
    gemm_kernel<<<dim3(1024, 2), 256>>>((const float*)pH, W_q, (u32*)pQh);
    attn_kernel<<<dim3(8, 8, 256), 256, ATTN_SMEM>>>(v, out);
}

// round 8
// speedup vs baseline: 1.4375x; 1.4375x over previous
#include <cuda_runtime.h>
#include <cuda_fp16.h>
#include <math.h>

#define B_ 256
#define T_ 512
#define N_ 512
#define H_ 256
#define CHUNK 64

typedef unsigned long long u64;
typedef unsigned u32;

// ---------------- scratch (device globals; allocation-free) ----------------
__device__ u32   g_Eh[(size_t)B_ * N_ * 64];    // E half2, h<128   [b][n][h2]
__device__ u32   g_Qh[(size_t)T_ * B_ * 64];    // Q half2, h<128   [t][b][h2]
__device__ float g_Ea[(size_t)B_ * N_ * 128];   // e^{2E}, h>=128   [b][n][hc]
__device__ float g_Qa[(size_t)T_ * B_ * 128];   // e^{2Q}, h>=128   [t][b][hc]
__device__ float g_Hall[(size_t)T_ * B_ * H_];  // hiddens f32 [t][b][h]
__device__ float g_hid[2][B_ * H_];             // double-buffered hid
__device__ float g_cell[B_ * H_];               // cell at chunk boundary
__device__ unsigned g_barcnt[16 * 32];          // 128B-padded barriers

// ---------------- fast-math helpers ----------------
__device__ __forceinline__ float tanha(float x) {
    float y; asm("tanh.approx.f32 %0, %1;" : "=f"(y) : "f"(x)); return y;
}
__device__ __forceinline__ float sigma_(float x) {
    return fmaf(0.5f, tanha(0.5f * x), 0.5f);
}
__device__ __forceinline__ u64 ffma2(u64 a, u64 b, u64 c) {
    u64 r; asm("fma.rn.f32x2 %0, %1, %2, %3;" : "=l"(r) : "l"(a), "l"(b), "l"(c));
    return r;
}
__device__ __forceinline__ u64 fmul2(u64 a, u64 b) {
    u64 r; asm("mul.rn.f32x2 %0, %1, %2;" : "=l"(r) : "l"(a), "l"(b));
    return r;
}
__device__ __forceinline__ u64 fdup2(float x) {
    u64 r; asm("mov.b64 %0, {%1, %1};" : "=l"(r) : "f"(x)); return r;
}
__device__ __forceinline__ float fsum2(u64 a) {
    float lo, hi; asm("mov.b64 {%0, %1}, %2;" : "=f"(lo), "=f"(hi) : "l"(a));
    return lo + hi;
}
__device__ __forceinline__ float2 funpk(u64 a) {
    float2 f; asm("mov.b64 {%0, %1}, %2;" : "=f"(f.x), "=f"(f.y) : "l"(a));
    return f;
}
__device__ __forceinline__ u32 packh2(float a, float b) {
    __half2 h = __floats2half2_rn(a, b);
    return *reinterpret_cast<u32*>(&h);
}
// half(low 16 bits) -> float, pure ALU (exact for normals)
__device__ __forceinline__ float h2f_fast(u32 hb) {
    u32 r = ((hb & 0x8000u) << 16) + ((hb & 0x7FFFu) << 13) + 0x38000000u;
    return __uint_as_float(r);
}
// XOR block swizzle for gemm W-tile smem
__device__ __forceinline__ int wperm(int k) {
    int b = k >> 3;
    return (((b ^ (b >> 2)) & 15) << 3) | (k & 7);
}
// packed Newton reciprocal: returns z2 = -1/u (rel err ~1e-5), u > 0 per lane
__device__ __forceinline__ u64 rcp_negz(u64 u, u64 M2, u64 P2) {
    u32 lo, hi;
    asm("mov.b64 {%0, %1}, %2;" : "=r"(lo), "=r"(hi) : "l"(u));
    lo = 0x7EF127EAu - lo;
    hi = 0x7EF127EAu - hi;
    u64 y0;
    asm("mov.b64 %0, {%1, %2};" : "=l"(y0) : "r"(lo), "r"(hi));
    u64 t1 = ffma2(u, y0, M2);   // u*y0 - 2
    u64 z1 = fmul2(y0, t1);      // -y1
    u64 t2 = ffma2(u, z1, P2);   // 2 + u*z1
    return fmul2(z1, t2);        // -y2  (y2 ~= 1/u)
}

// ---------------------------------------------------------------------------
// GEMM: for k<128 pack f16 -> OutH; for k>=128 write exp(2x) f32 -> OutA.
// Block (0,0) zeroes scan barrier counters (ordered by kernel boundaries).
// ---------------------------------------------------------------------------
__global__ __launch_bounds__(256) void gemm_kernel(
    const float* __restrict__ X, const float* __restrict__ W,
    u32* __restrict__ OutH, float* __restrict__ OutA) {
    __shared__ __align__(16) float Xs[16][132];
    __shared__ __align__(16) float Ws[16][132];
    const int tid = threadIdx.x;
    if (blockIdx.x == 0 && blockIdx.y == 0 && tid < 16) g_barcnt[tid * 32] = 0u;

    const size_t m0 = (size_t)blockIdx.x * 128;
    const int k0 = blockIdx.y * 128;
    const int f = tid & 3, r = tid >> 2;
    const int tm = tid >> 4, tk = tid & 15;
    const int wko = wperm(tk * 8);

    const float* Xp = X + (m0 + r) * H_ + f * 4;
    const float* Wp = W + (size_t)(k0 + r) * H_ + f * 4;
    const int rp0 = wperm(r), rp1 = wperm(r + 64);

    u64 acc[8][4];
#pragma unroll
    for (int i = 0; i < 8; i++)
#pragma unroll
        for (int j = 0; j < 4; j++) acc[i][j] = 0ULL;

    for (int h0 = 0; h0 < H_; h0 += 16) {
        float4 x0 = *(const float4*)(Xp + h0);
        float4 x1 = *(const float4*)(Xp + h0 + (size_t)64 * H_);
        float4 w0 = *(const float4*)(Wp + h0);
        float4 w1 = *(const float4*)(Wp + h0 + (size_t)64 * H_);
        __syncthreads();
        Xs[f * 4 + 0][r] = x0.x; Xs[f * 4 + 1][r] = x0.y;
        Xs[f * 4 + 2][r] = x0.z; Xs[f * 4 + 3][r] = x0.w;
        Xs[f * 4 + 0][r + 64] = x1.x; Xs[f * 4 + 1][r + 64] = x1.y;
        Xs[f * 4 + 2][r + 64] = x1.z; Xs[f * 4 + 3][r + 64] = x1.w;
        Ws[f * 4 + 0][rp0] = w0.x; Ws[f * 4 + 1][rp0] = w0.y;
        Ws[f * 4 + 2][rp0] = w0.z; Ws[f * 4 + 3][rp0] = w0.w;
        Ws[f * 4 + 0][rp1] = w1.x; Ws[f * 4 + 1][rp1] = w1.y;
        Ws[f * 4 + 2][rp1] = w1.z; Ws[f * 4 + 3][rp1] = w1.w;
        __syncthreads();
#pragma unroll
        for (int hh = 0; hh < 16; hh++) {
            float xr[8];
            *(float4*)&xr[0] = *(const float4*)&Xs[hh][tm * 8];
            *(float4*)&xr[4] = *(const float4*)&Xs[hh][tm * 8 + 4];
            ulonglong2 wa = *(const ulonglong2*)&Ws[hh][wko];
            ulonglong2 wb = *(const ulonglong2*)&Ws[hh][wko + 4];
#pragma unroll
            for (int i = 0; i < 8; i++) {
                u64 xd = fdup2(xr[i]);
                acc[i][0] = ffma2(xd, wa.x, acc[i][0]);
                acc[i][1] = ffma2(xd, wa.y, acc[i][1]);
                acc[i][2] = ffma2(xd, wb.x, acc[i][2]);
                acc[i][3] = ffma2(xd, wb.y, acc[i][3]);
            }
        }
    }
    if (k0 == 0) {
#pragma unroll
        for (int i = 0; i < 8; i++) {
            float2 p0 = funpk(acc[i][0]), p1 = funpk(acc[i][1]);
            float2 p2 = funpk(acc[i][2]), p3 = funpk(acc[i][3]);
            uint4 o;
            o.x = packh2(p0.x, p0.y); o.y = packh2(p1.x, p1.y);
            o.z = packh2(p2.x, p2.y); o.w = packh2(p3.x, p3.y);
            *(uint4*)(OutH + (m0 + tm * 8 + i) * 64 + tk * 4) = o;
        }
    } else {
#pragma unroll
        for (int i = 0; i < 8; i++) {
            float2 p0 = funpk(acc[i][0]), p1 = funpk(acc[i][1]);
            float2 p2 = funpk(acc[i][2]), p3 = funpk(acc[i][3]);
            float* op = OutA + (m0 + tm * 8 + i) * 128 + tk * 8;
            *(float4*)op = make_float4(__expf(2.f * p0.x), __expf(2.f * p0.y),
                                       __expf(2.f * p1.x), __expf(2.f * p1.y));
            *(float4*)(op + 4) = make_float4(__expf(2.f * p2.x), __expf(2.f * p2.y),
                                             __expf(2.f * p3.x), __expf(2.f * p3.y));
        }
    }
}

// ---------------------------------------------------------------------------
// LSTM scan chunk (R6 version, proven): 16 groups x 8 CTAs, 512 threads.
// ---------------------------------------------------------------------------
#define WSS 260
#define SCAN_SMEM ((128 * WSS + 16 * 256 + 8 * 16 * 128 + 128) * 4)

#define PDOT4(A, wv, hv)                 \
    A = ffma2((wv).x, (hv).x, A);        \
    A = ffma2((wv).y, (hv).y, A)

__global__ __launch_bounds__(512) void scan_kernel(
    const float* __restrict__ W_ih, const float* __restrict__ W_hh,
    const float* __restrict__ b_ih, const float* __restrict__ b_hh,
    int t0) {
    extern __shared__ float sm[];
    float* Ws = sm;                       // [128][WSS] gate-rows x h
    float* hid_s = Ws + 128 * WSS;        // [16][256]
    float* P = hid_s + 16 * 256;          // [8 hq][16 bat][128 gr]
    float* bcs = P + 8 * 16 * 128;        // [128]

    const int tid = threadIdx.x;
    const int grp = blockIdx.x >> 3, j = blockIdx.x & 7;
    const int r0 = grp * 16, hbase = j * 32;
    const int w = tid >> 5, lane = tid & 31;

    for (int idx = tid; idx < 128 * 256; idx += 512) {
        int q = idx >> 8, h = idx & 255;
        int row = (q >> 5) * 256 + hbase + (q & 31);
        size_t ww = (size_t)row * H_ + h;
        Ws[q * WSS + h] = W_ih[ww] + W_hh[ww];
    }
    if (tid < 128) {
        int row = (tid >> 5) * 256 + hbase + (tid & 31);
        bcs[tid] = b_ih[row] + b_hh[row];
    }
    float cell;
    if (t0 == 0) {
        for (int idx = tid; idx < 16 * 256; idx += 512) hid_s[idx] = 0.f;
        cell = 0.f;
    } else {
        const float4* src = (const float4*)&g_hid[t0 & 1][r0 * H_];
        for (int i2 = tid; i2 < 1024; i2 += 512)
            *(float4*)&hid_s[i2 * 4] = __ldcg(src + i2);
        cell = __ldcg(&g_cell[(r0 + w) * H_ + hbase + lane]);
    }
    __syncthreads();

    const int rh = w & 1, hq = w >> 1, hb = hq * 32;
    const float* wp0 = &Ws[(0 * 32 + lane) * WSS + hb];
    const float* wp1 = &Ws[(1 * 32 + lane) * WSS + hb];
    const float* wp2 = &Ws[(2 * 32 + lane) * WSS + hb];
    const float* wp3 = &Ws[(3 * 32 + lane) * WSS + hb];
    const float* hp = &hid_s[(rh * 8) * 256 + hb];
    float* pw = &P[hq * 2048 + (rh * 8) * 128 + lane];
    const float* pr = &P[w * 128 + lane];

    unsigned* barp = &g_barcnt[grp * 32];

    for (int tt = 0; tt < CHUNK; tt++) {
        const int t = t0 + tt;
        u64 acc[4][8];
#pragma unroll
        for (int g = 0; g < 4; g++)
#pragma unroll
            for (int r = 0; r < 8; r++) acc[g][r] = 0ULL;

#pragma unroll 2
        for (int c = 0; c < 32; c += 4) {
            ulonglong2 w0 = *(const ulonglong2*)(wp0 + c);
            ulonglong2 w1 = *(const ulonglong2*)(wp1 + c);
            ulonglong2 w2 = *(const ulonglong2*)(wp2 + c);
            ulonglong2 w3 = *(const ulonglong2*)(wp3 + c);
#pragma unroll
            for (int r = 0; r < 8; r++) {
                ulonglong2 hv = *(const ulonglong2*)(hp + r * 256 + c);
                PDOT4(acc[0][r], w0, hv);
                PDOT4(acc[1][r], w1, hv);
                PDOT4(acc[2][r], w2, hv);
                PDOT4(acc[3][r], w3, hv);
            }
        }
#pragma unroll
        for (int g = 0; g < 4; g++)
#pragma unroll
            for (int r = 0; r < 8; r++)
                pw[r * 128 + g * 32] = fsum2(acc[g][r]);
        __syncthreads();

        float gate[4];
#pragma unroll
        for (int ty = 0; ty < 4; ty++) {
            float s = bcs[ty * 32 + lane];
#pragma unroll
            for (int k = 0; k < 8; k++) s += pr[k * 2048 + ty * 32];
            gate[ty] = s;
        }
        cell = sigma_(gate[1]) * cell + sigma_(gate[0]) * tanha(gate[2]);
        float hd = sigma_(gate[3]) * tanha(cell);
        const int buf = (t + 1) & 1;
        g_hid[buf][(r0 + w) * H_ + hbase + lane] = hd;
        g_Hall[((size_t)t * B_ + r0 + w) * H_ + hbase + lane] = hd;

        __syncthreads();
        if (tid == 0) {
            asm volatile("red.release.gpu.global.add.u32 [%0], %1;"
                         :: "l"(barp), "r"(1u) : "memory");
            unsigned tgt = (unsigned)(t + 1) * 8u, cur;
            do {
                asm volatile("ld.acquire.gpu.global.u32 %0, [%1];"
                             : "=r"(cur) : "l"(barp) : "memory");
            } while (cur < tgt);
        }
        __syncthreads();

        const float4* src = (const float4*)&g_hid[buf][r0 * H_];
        for (int i2 = tid; i2 < 1024; i2 += 512)
            *(float4*)&hid_s[i2 * 4] = __ldcg(src + i2);
        __syncthreads();
    }

    g_cell[(r0 + w) * H_ + hbase + lane] = cell;
}

// ---------------------------------------------------------------------------
// Attention hybrid:
//   h<128:  HADD2 -> tanh.f16x2 (MUFU) -> HFMA2 -> ALU widen
//   h>=128: tanh(E+Q) = 1 - 2/(1+ab), ab from precomputed exps; packed-f32x2
//           Newton reciprocal on the FMA pipe (no MUFU).
// ---------------------------------------------------------------------------
#define HSTR 68
#define ASTR 132
#define ATTN_SMEM (2 * 64 * HSTR * 4 + 2 * 64 * ASTR * 4 + 64 * 4 + 64 * 8)

#define HADD2A(r, a, b) asm("add.rn.f16x2 %0, %1, %2;" : "=r"(r) : "r"(a), "r"(b))
#define TANH2A(r, a)    asm("tanh.approx.f16x2 %0, %1;" : "=r"(r) : "r"(a))
#define HFMA2A(d, a, b) asm("fma.rn.f16x2 %0, %1, %2, %3;" : "=r"(d) : "r"(a), "r"(b), "r"(d))

#define ATC(accr, qc, ec, vc)            \
    { u32 s_, t_;                        \
      HADD2A(s_, (qc), (ec));            \
      TANH2A(t_, s_);                    \
      HFMA2A((accr), (vc), t_); }

#define AT4H(accr, q4, e4, v4)           \
    ATC(accr, (q4).x, (e4).x, (v4).x);   \
    ATC(accr, (q4).y, (e4).y, (v4).y);   \
    ATC(accr, (q4).z, (e4).z, (v4).z);   \
    ATC(accr, (q4).w, (e4).w, (v4).w)

__global__ __launch_bounds__(256) void attn_kernel(
    const float* __restrict__ v, float* __restrict__ out) {
    extern __shared__ u32 smu[];
    u32* Qh = smu;                          // [64][HSTR] half2, h<128
    u32* Eh = Qh + 64 * HSTR;               // [64][HSTR]
    float* Qa = (float*)(Eh + 64 * HSTR);   // [64][ASTR] e^{2Q}, h>=128
    float* Ea = Qa + 64 * ASTR;             // [64][ASTR]
    u32* vh = (u32*)(Ea + 64 * ASTR);       // [64] half2
    u64* vf = (u64*)(vh + 64);              // [64] f32x2

    const int tid = threadIdx.x;
    const int b = blockIdx.z, t0 = blockIdx.y << 6, n0 = blockIdx.x << 6;

    if (tid < 64) {
        float2 vv = ((const float2*)v)[tid];
        vh[tid] = packh2(vv.x, vv.y);
    } else if (tid < 128) {
        int k = tid - 64;
        ((float2*)vf)[k] = ((const float2*)v)[64 + k];
    }
    for (int i = tid; i < 1024; i += 256) {
        int row = i >> 4, c = i & 15;
        ((uint4*)&Qh[row * HSTR])[c] =
            ((const uint4*)(g_Qh + ((size_t)(t0 + row) * B_ + b) * 64))[c];
        ((uint4*)&Eh[row * HSTR])[c] =
            ((const uint4*)(g_Eh + ((size_t)b * N_ + n0 + row) * 64))[c];
    }
    for (int i = tid; i < 2048; i += 256) {
        int row = i >> 5, c = i & 31;
        ((uint4*)&Qa[row * ASTR])[c] =
            ((const uint4*)(g_Qa + ((size_t)(t0 + row) * B_ + b) * 128))[c];
        ((uint4*)&Ea[row * ASTR])[c] =
            ((const uint4*)(g_Ea + ((size_t)b * N_ + n0 + row) * 128))[c];
    }
    __syncthreads();

    const int tx = tid & 15, ty = tid >> 4;
    float acc[4][4];
#pragma unroll
    for (int i = 0; i < 4; i++)
#pragma unroll
        for (int jj = 0; jj < 4; jj++) acc[i][jj] = 0.f;

    // ---- phase 1: f16 MUFU path, h < 128 ----
    {
        const u32* qp = &Qh[ty * HSTR];
        const u32* ep = &Eh[tx * HSTR];
#pragma unroll 1
        for (int c = 0; c < 8; c++) {
            u32 hacc[4][4];
#pragma unroll
            for (int i = 0; i < 4; i++)
#pragma unroll
                for (int jj = 0; jj < 4; jj++) hacc[i][jj] = 0u;
#pragma unroll
            for (int s = 0; s < 2; s++) {
                const int o = (c * 2 + s) * 4;
                uint4 vv = *(const uint4*)&vh[o];
                uint4 q0 = *(const uint4*)(qp + o);
                uint4 q1 = *(const uint4*)(qp + 16 * HSTR + o);
                uint4 q2 = *(const uint4*)(qp + 32 * HSTR + o);
                uint4 q3 = *(const uint4*)(qp + 48 * HSTR + o);
                uint4 e0 = *(const uint4*)(ep + o);
                uint4 e1 = *(const uint4*)(ep + 16 * HSTR + o);
                uint4 e2 = *(const uint4*)(ep + 32 * HSTR + o);
                uint4 e3 = *(const uint4*)(ep + 48 * HSTR + o);
                AT4H(hacc[0][0], q0, e0, vv); AT4H(hacc[0][1], q0, e1, vv);
                AT4H(hacc[0][2], q0, e2, vv); AT4H(hacc[0][3], q0, e3, vv);
                AT4H(hacc[1][0], q1, e0, vv); AT4H(hacc[1][1], q1, e1, vv);
                AT4H(hacc[1][2], q1, e2, vv); AT4H(hacc[1][3], q1, e3, vv);
                AT4H(hacc[2][0], q2, e0, vv); AT4H(hacc[2][1], q2, e1, vv);
                AT4H(hacc[2][2], q2, e2, vv); AT4H(hacc[2][3], q2, e3, vv);
                AT4H(hacc[3][0], q3, e0, vv); AT4H(hacc[3][1], q3, e1, vv);
                AT4H(hacc[3][2], q3, e2, vv); AT4H(hacc[3][3], q3, e3, vv);
            }
#pragma unroll
            for (int i = 0; i < 4; i++)
#pragma unroll
                for (int jj = 0; jj < 4; jj++) {
                    u32 hb = hacc[i][jj];
                    acc[i][jj] += h2f_fast(hb) + h2f_fast(hb >> 16);
                }
        }
    }

    // ---- phase 2: exp/Newton FMA path, h >= 128 ----
    {
        const u64 ONES = fdup2(1.f), M2 = fdup2(-2.f), P2 = fdup2(2.f);
        const u64* bp = (const u64*)&Qa[ty * ASTR];
        const u64* ap = (const u64*)&Ea[tx * ASTR];
        u64 acc2[4][4];
#pragma unroll
        for (int i = 0; i < 4; i++)
#pragma unroll
            for (int jj = 0; jj < 4; jj++) acc2[i][jj] = 0ULL;

#pragma unroll 2
        for (int hp = 0; hp < 64; hp++) {
            u64 vv = vf[hp];
            u64 b0 = bp[hp];
            u64 b1 = bp[hp + 16 * (ASTR / 2)];
            u64 b2 = bp[hp + 32 * (ASTR / 2)];
            u64 b3 = bp[hp + 48 * (ASTR / 2)];
            u64 a0 = ap[hp];
            u64 a1 = ap[hp + 16 * (ASTR / 2)];
            u64 a2 = ap[hp + 32 * (ASTR / 2)];
            u64 a3 = ap[hp + 48 * (ASTR / 2)];
            u64 bb[4] = {b0, b1, b2, b3};
            u64 aa[4] = {a0, a1, a2, a3};
#pragma unroll
            for (int i = 0; i < 4; i++)
#pragma unroll
                for (int jj = 0; jj < 4; jj++) {
                    u64 u = ffma2(aa[jj], bb[i], ONES);
                    u64 z2 = rcp_negz(u, M2, P2);        // -1/u
                    acc2[i][jj] = ffma2(vv, z2, acc2[i][jj]);
                }
        }

        float vsum = 0.f;
#pragma unroll 8
        for (int k = 0; k < 64; k++) vsum += fsum2(vf[k]);
#pragma unroll
        for (int i = 0; i < 4; i++)
#pragma unroll
            for (int jj = 0; jj < 4; jj++)
                acc[i][jj] += vsum + 2.f * fsum2(acc2[i][jj]);
    }

#pragma unroll
    for (int i = 0; i < 4; i++) {
        float* op = out + ((size_t)b * T_ + t0 + ty + 16 * i) * N_ + n0 + tx;
#pragma unroll
        for (int jj = 0; jj < 4; jj++) op[16 * jj] = acc[i][jj];
    }
}

// ---------------------------------------------------------------------------
extern "C" void kernel_launch(void* const* d_in, const int* in_sizes, int n_in,
                              void* d_out, int out_size) {
    const float* enc   = (const float*)d_in[0];
    const float* W_ih  = (const float*)d_in[1];
    const float* W_hh  = (const float*)d_in[2];
    const float* b_ih  = (const float*)d_in[3];
    const float* b_hh  = (const float*)d_in[4];
    const float* W_ref = (const float*)d_in[5];
    const float* W_q   = (const float*)d_in[6];
    const float* v     = (const float*)d_in[7];
    float* out = (float*)d_out;

    cudaFuncSetAttribute(scan_kernel, cudaFuncAttributeMaxDynamicSharedMemorySize, SCAN_SMEM);
    cudaFuncSetAttribute(attn_kernel, cudaFuncAttributeMaxDynamicSharedMemorySize, ATTN_SMEM);

    void *pEh, *pQh, *pEa, *pQa, *pH;
    cudaGetSymbolAddress(&pEh, g_Eh);
    cudaGetSymbolAddress(&pQh, g_Qh);
    cudaGetSymbolAddress(&pEa, g_Ea);
    cudaGetSymbolAddress(&pQa, g_Qa);
    cudaGetSymbolAddress(&pH, g_Hall);

    gemm_kernel<<<dim3(1024, 2), 256>>>(enc, W_ref, (u32*)pEh, (float*)pEa);
    for (int t0 = 0; t0 < T_; t0 += CHUNK)
        scan_kernel<<<128, 512, SCAN_SMEM>>>(W_ih, W_hh, b_ih, b_hh, t0);
    gemm_kernel<<<dim3(1024, 2), 256>>>((const float*)pH, W_q, (u32*)pQh, (float*)pQa);
    attn_kernel<<<dim3(8, 8, 256), 256, ATTN_SMEM>>>(v, out);
}